// round 1
// baseline (speedup 1.0000x reference)
#include <cuda_runtime.h>

#define NB 32
#define NC 256
#define NH 64
#define NW 64
#define NM 16
#define EPSV 1e-5f

// Scratch (allocation-free rule: __device__ globals)
__device__ __align__(16) float g_xh[NB*NC*NH];       // mean over w: (b,c,h)
__device__ __align__(16) float g_xw[NB*NC*NW];       // mean over h: (b,c,w)
__device__ __align__(16) float g_pooled[NB*NC];      // mean over (h,w)
__device__ __align__(16) float g_chansum[NB*NH*NW];  // sum over c
__device__ __align__(16) float g_fch[NB*NC];
__device__ __align__(16) float g_fsa[NB*NH*NW];
__device__ __align__(16) float g_sh[NB*NC*NH];
__device__ __align__(16) float g_sw[NB*NC*NW];

__global__ void k_zero() {
    int i = blockIdx.x * 256 + threadIdx.x;
    ((float4*)g_chansum)[i] = make_float4(0.f, 0.f, 0.f, 0.f);
}

// Pass 1: one block per (b, chunk of 8 channels). Computes x_h, x_w, pooled,
// and accumulates channel-sum (8 channels pre-reduced in registers -> atomics).
__global__ __launch_bounds__(256) void k_reduce(const float* __restrict__ x) {
    int b = blockIdx.y, chunk = blockIdx.x, t = threadIdx.x;
    int lane = t & 31, warp = t >> 5;
    __shared__ float4 s_col[8][16];
    float4 ch[4];
#pragma unroll
    for (int i = 0; i < 4; i++) ch[i] = make_float4(0.f, 0.f, 0.f, 0.f);

    for (int ci = 0; ci < 8; ci++) {
        int c = chunk * 8 + ci;
        const float4* plane = (const float4*)x + (size_t)(b * NC + c) * 1024;
        float4 cacc = make_float4(0.f, 0.f, 0.f, 0.f);
#pragma unroll
        for (int i = 0; i < 4; i++) {
            int q = i * 256 + t;          // float4 index; row = q>>4, wquad = q&15
            float4 v = plane[q];
            ch[i].x += v.x; ch[i].y += v.y; ch[i].z += v.z; ch[i].w += v.w;
            cacc.x += v.x; cacc.y += v.y; cacc.z += v.z; cacc.w += v.w;
            // row sum across the 16 lanes covering one row
            float rs = v.x + v.y + v.z + v.w;
            rs += __shfl_xor_sync(0xffffffffu, rs, 8);
            rs += __shfl_xor_sync(0xffffffffu, rs, 4);
            rs += __shfl_xor_sync(0xffffffffu, rs, 2);
            rs += __shfl_xor_sync(0xffffffffu, rs, 1);
            if ((t & 15) == 0)
                g_xh[(b * NC + c) * NH + (q >> 4)] = rs * (1.f / NW);
        }
        // column sums: combine the two 16-lane halves within the warp
        cacc.x += __shfl_xor_sync(0xffffffffu, cacc.x, 16);
        cacc.y += __shfl_xor_sync(0xffffffffu, cacc.y, 16);
        cacc.z += __shfl_xor_sync(0xffffffffu, cacc.z, 16);
        cacc.w += __shfl_xor_sync(0xffffffffu, cacc.w, 16);
        if (lane < 16) s_col[warp][lane] = cacc;
        __syncthreads();
        if (t < 16) {
            float4 s = s_col[0][t];
#pragma unroll
            for (int wv = 1; wv < 8; wv++) {
                float4 p = s_col[wv][t];
                s.x += p.x; s.y += p.y; s.z += p.z; s.w += p.w;
            }
            ((float4*)g_xw)[(b * NC + c) * 16 + t] =
                make_float4(s.x * (1.f / NH), s.y * (1.f / NH),
                            s.z * (1.f / NH), s.w * (1.f / NH));
            float tot = s.x + s.y + s.z + s.w;
            tot += __shfl_xor_sync(0xffffu, tot, 8);
            tot += __shfl_xor_sync(0xffffu, tot, 4);
            tot += __shfl_xor_sync(0xffffu, tot, 2);
            tot += __shfl_xor_sync(0xffffu, tot, 1);
            if (t == 0) g_pooled[b * NC + c] = tot * (1.f / (NH * NW));
        }
        __syncthreads();
    }
    // channel-sum accumulation (8 channels pre-reduced)
    float* cs = g_chansum + b * NH * NW;
#pragma unroll
    for (int i = 0; i < 4; i++) {
        int q = i * 256 + t;
        atomicAdd(cs + 4 * q + 0, ch[i].x);
        atomicAdd(cs + 4 * q + 1, ch[i].y);
        atomicAdd(cs + 4 * q + 2, ch[i].z);
        atomicAdd(cs + 4 * q + 3, ch[i].w);
    }
}

// Small math: f_ch, y = w10 @ cat -> BN -> relu, s_h/s_w = sigmoid(w11 @ y).
// One block per b, 256 threads.
__global__ __launch_bounds__(256) void k_attn(
    const float* __restrict__ w10, const float* __restrict__ w11,
    const float* __restrict__ gamma, const float* __restrict__ beta,
    const float* __restrict__ mean, const float* __restrict__ var,
    const float* __restrict__ w20) {
    int b = blockIdx.x, t = threadIdx.x;
    __shared__ float s_w10[NM * NC];   // [m][c]
    __shared__ float s_w11[NC * NM];   // [c][m]
    __shared__ float s_y[NM * 128];    // [m][l]
    __shared__ float s_pool[NC];
    __shared__ float s_inv[NM], s_bias[NM];

#pragma unroll
    for (int i = 0; i < 16; i++) {
        s_w10[i * 256 + t] = w10[i * 256 + t];
        s_w11[i * 256 + t] = w11[i * 256 + t];
    }
    s_pool[t] = g_pooled[b * NC + t];
    if (t < NM) {
        float inv = rsqrtf(var[t] + EPSV) * gamma[t];
        s_inv[t] = inv;
        s_bias[t] = beta[t] - mean[t] * inv;
    }
    __syncthreads();

    // f_ch: 5-tap SAME cross-correlation along c
    {
        float acc = 0.f;
#pragma unroll
        for (int k = 0; k < 5; k++) {
            int cc = t + k - 2;
            if (cc >= 0 && cc < NC) acc += s_pool[cc] * w20[k];
        }
        g_fch[b * NC + t] = acc;
    }

    // y[m][l] = sum_c w10[m][c] * cat[b][c][l]; thread -> (l, 8 m's)
    int l = t & 127;
    int mb = (t >> 7) * 8;
    float y[8];
#pragma unroll
    for (int j = 0; j < 8; j++) y[j] = 0.f;
    const float* catp = (l < 64) ? (g_xh + (size_t)(b * NC) * 64 + l)
                                 : (g_xw + (size_t)(b * NC) * 64 + (l - 64));
    for (int c = 0; c < NC; c++) {
        float cv = catp[(size_t)c * 64];
#pragma unroll
        for (int j = 0; j < 8; j++)
            y[j] = fmaf(s_w10[(mb + j) * NC + c], cv, y[j]);
    }
#pragma unroll
    for (int j = 0; j < 8; j++) {
        int m = mb + j;
        s_y[m * 128 + l] = fmaxf(fmaf(y[j], s_inv[m], s_bias[m]), 0.f);
    }
    __syncthreads();

    // s_h/s_w: sigmoid(sum_m w11[c][m] * y[m][l]); hoist y column to regs
    float yr[16];
#pragma unroll
    for (int m = 0; m < 16; m++) yr[m] = s_y[m * 128 + l];
    int c0 = t >> 7;
    for (int it = 0; it < 128; it++) {
        int c = c0 + it * 2;
        float a = 0.f;
#pragma unroll
        for (int m = 0; m < 16; m++)
            a = fmaf(s_w11[c * NM + m], yr[m], a);
        float v = 1.f / (1.f + expf(-a));
        if (l < 64) g_sh[(size_t)(b * NC + c) * 64 + l] = v;
        else        g_sw[(size_t)(b * NC + c) * 64 + (l - 64)] = v;
    }
}

// f_sa: sigmoid(conv3x3(mean over c of x)), SAME zero pad. One block per b.
__global__ __launch_bounds__(256) void k_fsa(const float* __restrict__ w21) {
    int b = blockIdx.x, t = threadIdx.x;
    __shared__ float s_m[NH * NW];
    __shared__ float s_k[9];
    if (t < 9) s_k[t] = w21[t];
#pragma unroll
    for (int i = 0; i < 16; i++)
        s_m[i * 256 + t] = g_chansum[b * 4096 + i * 256 + t] * (1.f / NC);
    __syncthreads();
#pragma unroll
    for (int i = 0; i < 16; i++) {
        int p = i * 256 + t;
        int h = p >> 6, w = p & 63;
        float acc = 0.f;
#pragma unroll
        for (int dh = -1; dh <= 1; dh++) {
#pragma unroll
            for (int dw = -1; dw <= 1; dw++) {
                int hh = h + dh, ww = w + dw;
                if (hh >= 0 && hh < NH && ww >= 0 && ww < NW)
                    acc += s_m[hh * 64 + ww] * s_k[(dh + 1) * 3 + (dw + 1)];
            }
        }
        g_fsa[b * 4096 + p] = 1.f / (1.f + expf(-acc));
    }
}

// Pass 2: out = x * (f_ch + s_h*s_w + f_sa). One block per (b,c) plane.
__global__ __launch_bounds__(256) void k_final(const float* __restrict__ x,
                                               float* __restrict__ out) {
    int b = blockIdx.y, c = blockIdx.x, t = threadIdx.x;
    int bc = b * NC + c;
    __shared__ float s_sh[64], s_sw[64];
    if (t < 64) s_sh[t] = g_sh[(size_t)bc * 64 + t];
    else if (t < 128) s_sw[t - 64] = g_sw[(size_t)bc * 64 + (t - 64)];
    float fch = g_fch[bc];
    __syncthreads();
    const float4* xp = (const float4*)x + (size_t)bc * 1024;
    float4* op = (float4*)out + (size_t)bc * 1024;
    const float4* fp = (const float4*)g_fsa + (size_t)b * 1024;
#pragma unroll
    for (int i = 0; i < 4; i++) {
        int q = i * 256 + t;
        float4 xv = xp[q];
        float4 fv = fp[q];
        float sh = s_sh[q >> 4];
        int w4 = (q & 15) * 4;
        float4 o;
        o.x = xv.x * (fch + sh * s_sw[w4 + 0] + fv.x);
        o.y = xv.y * (fch + sh * s_sw[w4 + 1] + fv.y);
        o.z = xv.z * (fch + sh * s_sw[w4 + 2] + fv.z);
        o.w = xv.w * (fch + sh * s_sw[w4 + 3] + fv.w);
        op[q] = o;
    }
}

extern "C" void kernel_launch(void* const* d_in, const int* in_sizes, int n_in,
                              void* d_out, int out_size) {
    const float* x     = (const float*)d_in[0];
    const float* w10   = (const float*)d_in[1];
    const float* w11   = (const float*)d_in[2];
    const float* gamma = (const float*)d_in[3];
    const float* beta  = (const float*)d_in[4];
    const float* mean  = (const float*)d_in[5];
    const float* var   = (const float*)d_in[6];
    const float* w20   = (const float*)d_in[7];
    const float* w21   = (const float*)d_in[8];
    float* out = (float*)d_out;

    k_zero<<<NB * NH * NW / 4 / 256, 256>>>();
    k_reduce<<<dim3(32, NB), 256>>>(x);
    k_attn<<<NB, 256>>>(w10, w11, gamma, beta, mean, var, w20);
    k_fsa<<<NB, 256>>>(w21);
    k_final<<<dim3(NC, NB), 256>>>(x, out);
}

// round 3
// speedup vs baseline: 1.0223x; 1.0223x over previous
#include <cuda_runtime.h>

#define NB 32
#define NC 256
#define NH 64
#define NW 64
#define NM 16
#define EPSV 1e-5f

// Scratch (allocation-free rule: __device__ globals)
__device__ __align__(16) float g_xh[NB*NC*NH];       // mean over w: (b,c,h)
__device__ __align__(16) float g_xw[NB*NC*NW];       // mean over h: (b,c,w)
__device__ __align__(16) float g_pooled[NB*NC];      // mean over (h,w)
__device__ __align__(16) float g_chansum[NB*NH*NW];  // sum over c
__device__ __align__(16) float g_fch[NB*NC];
__device__ __align__(16) float g_fsa[NB*NH*NW];
__device__ __align__(16) float g_sh[NB*NC*NH];
__device__ __align__(16) float g_sw[NB*NC*NW];

__global__ void k_zero() {
    int i = blockIdx.x * 256 + threadIdx.x;
    ((float4*)g_chansum)[i] = make_float4(0.f, 0.f, 0.f, 0.f);
}

// Pass 1: one block per (b, chunk of 8 channels). Computes x_h, x_w, pooled,
// and accumulates channel-sum (8 channels pre-reduced in registers -> atomics).
__global__ __launch_bounds__(256) void k_reduce(const float* __restrict__ x) {
    int b = blockIdx.y, chunk = blockIdx.x, t = threadIdx.x;
    int lane = t & 31, warp = t >> 5;
    __shared__ float4 s_col[8][16];
    float4 ch[4];
#pragma unroll
    for (int i = 0; i < 4; i++) ch[i] = make_float4(0.f, 0.f, 0.f, 0.f);

    for (int ci = 0; ci < 8; ci++) {
        int c = chunk * 8 + ci;
        const float4* plane = (const float4*)x + (size_t)(b * NC + c) * 1024;
        float4 cacc = make_float4(0.f, 0.f, 0.f, 0.f);
#pragma unroll
        for (int i = 0; i < 4; i++) {
            int q = i * 256 + t;          // float4 index; row = q>>4, wquad = q&15
            float4 v = __ldcs(plane + q);
            ch[i].x += v.x; ch[i].y += v.y; ch[i].z += v.z; ch[i].w += v.w;
            cacc.x += v.x; cacc.y += v.y; cacc.z += v.z; cacc.w += v.w;
            // row sum across the 16 lanes covering one row
            float rs = v.x + v.y + v.z + v.w;
            rs += __shfl_xor_sync(0xffffffffu, rs, 8);
            rs += __shfl_xor_sync(0xffffffffu, rs, 4);
            rs += __shfl_xor_sync(0xffffffffu, rs, 2);
            rs += __shfl_xor_sync(0xffffffffu, rs, 1);
            if ((t & 15) == 0)
                g_xh[(b * NC + c) * NH + (q >> 4)] = rs * (1.f / NW);
        }
        // column sums: combine the two 16-lane halves within the warp
        cacc.x += __shfl_xor_sync(0xffffffffu, cacc.x, 16);
        cacc.y += __shfl_xor_sync(0xffffffffu, cacc.y, 16);
        cacc.z += __shfl_xor_sync(0xffffffffu, cacc.z, 16);
        cacc.w += __shfl_xor_sync(0xffffffffu, cacc.w, 16);
        if (lane < 16) s_col[warp][lane] = cacc;
        __syncthreads();
        if (t < 16) {
            float4 s = s_col[0][t];
#pragma unroll
            for (int wv = 1; wv < 8; wv++) {
                float4 p = s_col[wv][t];
                s.x += p.x; s.y += p.y; s.z += p.z; s.w += p.w;
            }
            ((float4*)g_xw)[(b * NC + c) * 16 + t] =
                make_float4(s.x * (1.f / NH), s.y * (1.f / NH),
                            s.z * (1.f / NH), s.w * (1.f / NH));
            float tot = s.x + s.y + s.z + s.w;
            tot += __shfl_xor_sync(0xffffu, tot, 8);
            tot += __shfl_xor_sync(0xffffu, tot, 4);
            tot += __shfl_xor_sync(0xffffu, tot, 2);
            tot += __shfl_xor_sync(0xffffu, tot, 1);
            if (t == 0) g_pooled[b * NC + c] = tot * (1.f / (NH * NW));
        }
        __syncthreads();
    }
    // channel-sum accumulation (8 channels pre-reduced)
    float* cs = g_chansum + b * NH * NW;
#pragma unroll
    for (int i = 0; i < 4; i++) {
        int q = i * 256 + t;
        atomicAdd(cs + 4 * q + 0, ch[i].x);
        atomicAdd(cs + 4 * q + 1, ch[i].y);
        atomicAdd(cs + 4 * q + 2, ch[i].z);
        atomicAdd(cs + 4 * q + 3, ch[i].w);
    }
}

// Fused middle kernel:
//  blocks [0,128):  attention MLP, block = (b, l-group of 32). 128 threads.
//  blocks [128,384): f_sa 3x3 conv + f_ch 5-tap, block = (b, pixel chunk of 512).
__global__ __launch_bounds__(128) void k_mid(
    const float* __restrict__ w10, const float* __restrict__ w11,
    const float* __restrict__ gamma, const float* __restrict__ beta,
    const float* __restrict__ mean, const float* __restrict__ var,
    const float* __restrict__ w20, const float* __restrict__ w21) {
    int bx = blockIdx.x, t = threadIdx.x;
    __shared__ float s_w10t[NC * NM];  // transposed: [c][m]
    __shared__ float s_w11[NC * NM];   // [c][m] (native layout)
    __shared__ float s_y[NM * 32];     // [m][lsub]
    __shared__ float s_inv[NM], s_bias[NM];

    if (bx < 128) {
        int b = bx >> 2, lg = bx & 3;
        int lsub = t & 31, grp = t >> 5;   // grp: whole-warp constant (0..3)
        int l = lg * 32 + lsub;            // 0..127; lg<2 -> h-branch, lg>=2 -> w
#pragma unroll
        for (int k = 0; k < 32; k++) {
            int idx = k * 128 + t;
            int m = idx >> 8, c = idx & 255;
            s_w10t[c * NM + m] = w10[idx];
            s_w11[idx] = w11[idx];
        }
        if (t < NM) {
            float inv = rsqrtf(var[t] + EPSV) * gamma[t];
            s_inv[t] = inv;
            s_bias[t] = beta[t] - mean[t] * inv;
        }
        __syncthreads();

        // phase 1: y[m][l] = sum_c w10[m][c]*cat[c][l], 4 m's per thread
        const float* catp = (l < 64) ? g_xh + (size_t)b * NC * 64 + l
                                     : g_xw + (size_t)b * NC * 64 + (l - 64);
        float a0 = 0.f, a1 = 0.f, a2 = 0.f, a3 = 0.f;
#pragma unroll 4
        for (int c = 0; c < NC; c++) {
            float cv = __ldg(catp + (size_t)c * 64);
            float4 wv = *(const float4*)&s_w10t[c * NM + grp * 4];
            a0 = fmaf(wv.x, cv, a0);
            a1 = fmaf(wv.y, cv, a1);
            a2 = fmaf(wv.z, cv, a2);
            a3 = fmaf(wv.w, cv, a3);
        }
        int m0 = grp * 4;
        s_y[(m0 + 0) * 32 + lsub] = fmaxf(fmaf(a0, s_inv[m0 + 0], s_bias[m0 + 0]), 0.f);
        s_y[(m0 + 1) * 32 + lsub] = fmaxf(fmaf(a1, s_inv[m0 + 1], s_bias[m0 + 1]), 0.f);
        s_y[(m0 + 2) * 32 + lsub] = fmaxf(fmaf(a2, s_inv[m0 + 2], s_bias[m0 + 2]), 0.f);
        s_y[(m0 + 3) * 32 + lsub] = fmaxf(fmaf(a3, s_inv[m0 + 3], s_bias[m0 + 3]), 0.f);
        __syncthreads();

        // phase 2: s = sigmoid(sum_m w11[c][m]*y[m][l]); y column in regs
        float yr[NM];
#pragma unroll
        for (int m = 0; m < NM; m++) yr[m] = s_y[m * 32 + lsub];
        float* dst = (l < 64) ? g_sh + (size_t)b * NC * 64 + l
                              : g_sw + (size_t)b * NC * 64 + (l - 64);
#pragma unroll 4
        for (int it = 0; it < 64; it++) {
            int c = it * 4 + grp;
            const float4* wr = (const float4*)&s_w11[c * NM];
            float4 w0 = wr[0], w1 = wr[1], w2 = wr[2], w3 = wr[3];
            float a = 0.f;
            a = fmaf(w0.x, yr[0], a);  a = fmaf(w0.y, yr[1], a);
            a = fmaf(w0.z, yr[2], a);  a = fmaf(w0.w, yr[3], a);
            a = fmaf(w1.x, yr[4], a);  a = fmaf(w1.y, yr[5], a);
            a = fmaf(w1.z, yr[6], a);  a = fmaf(w1.w, yr[7], a);
            a = fmaf(w2.x, yr[8], a);  a = fmaf(w2.y, yr[9], a);
            a = fmaf(w2.z, yr[10], a); a = fmaf(w2.w, yr[11], a);
            a = fmaf(w3.x, yr[12], a); a = fmaf(w3.y, yr[13], a);
            a = fmaf(w3.z, yr[14], a); a = fmaf(w3.w, yr[15], a);
            dst[(size_t)c * 64] = 1.f / (1.f + __expf(-a));
        }
    } else {
        // f_sa + f_ch role
        int idx = bx - 128;
        int b = idx >> 3, chunk = idx & 7;
        const float* cs = g_chansum + (size_t)b * 4096;

        if (chunk == 0) {
            // f_ch: 5-tap SAME conv over pooled channels (2 c per thread)
#pragma unroll
            for (int r = 0; r < 2; r++) {
                int cc = r * 128 + t;
                float acc = 0.f;
#pragma unroll
                for (int k = 0; k < 5; k++) {
                    int c2 = cc + k - 2;
                    if (c2 >= 0 && c2 < NC)
                        acc += __ldg(&g_pooled[b * NC + c2]) * w20[k];
                }
                g_fch[b * NC + cc] = acc;
            }
        }
        float kk[9];
#pragma unroll
        for (int i = 0; i < 9; i++) kk[i] = w21[i];
        int p0 = chunk * 512 + t * 4;
        int h = p0 >> 6, wbase = p0 & 63;
        float4 o;
        float* op = (float*)&o;
#pragma unroll
        for (int j = 0; j < 4; j++) {
            int w = wbase + j;
            float acc = 0.f;
#pragma unroll
            for (int dh = -1; dh <= 1; dh++) {
                int hh = h + dh;
                if (hh < 0 || hh >= NH) continue;
#pragma unroll
                for (int dw = -1; dw <= 1; dw++) {
                    int ww = w + dw;
                    if (ww < 0 || ww >= NW) continue;
                    acc += __ldg(cs + hh * 64 + ww) * kk[(dh + 1) * 3 + (dw + 1)];
                }
            }
            op[j] = 1.f / (1.f + __expf(-acc * (1.f / NC)));
        }
        ((float4*)g_fsa)[((size_t)b * 4096 + p0) >> 2] = o;
    }
}

// Pass 2: out = x * (f_ch + s_h*s_w + f_sa). One block per (b,c) plane.
__global__ __launch_bounds__(256) void k_final(const float* __restrict__ x,
                                               float* __restrict__ out) {
    int b = blockIdx.y, c = blockIdx.x, t = threadIdx.x;
    int bc = b * NC + c;
    __shared__ float s_sh[64];
    __shared__ __align__(16) float s_sw[64];
    if (t < 64) s_sh[t] = g_sh[(size_t)bc * 64 + t];
    else if (t < 128) s_sw[t - 64] = g_sw[(size_t)bc * 64 + (t - 64)];
    float fch = g_fch[bc];
    __syncthreads();
    const float4* xp = (const float4*)x + (size_t)bc * 1024;
    float4* op = (float4*)out + (size_t)bc * 1024;
    const float4* fp = (const float4*)g_fsa + (size_t)b * 1024;
#pragma unroll
    for (int i = 0; i < 4; i++) {
        int q = i * 256 + t;
        float4 xv = __ldcs(xp + q);
        float4 fv = __ldg(fp + q);
        float sh = s_sh[q >> 4];
        float4 swv = ((const float4*)s_sw)[q & 15];
        float4 o;
        o.x = xv.x * (fch + sh * swv.x + fv.x);
        o.y = xv.y * (fch + sh * swv.y + fv.y);
        o.z = xv.z * (fch + sh * swv.z + fv.z);
        o.w = xv.w * (fch + sh * swv.w + fv.w);
        __stcs(op + q, o);
    }
}

extern "C" void kernel_launch(void* const* d_in, const int* in_sizes, int n_in,
                              void* d_out, int out_size) {
    const float* x     = (const float*)d_in[0];
    const float* w10   = (const float*)d_in[1];
    const float* w11   = (const float*)d_in[2];
    const float* gamma = (const float*)d_in[3];
    const float* beta  = (const float*)d_in[4];
    const float* mean  = (const float*)d_in[5];
    const float* var   = (const float*)d_in[6];
    const float* w20   = (const float*)d_in[7];
    const float* w21   = (const float*)d_in[8];
    float* out = (float*)d_out;

    k_zero<<<NB * NH * NW / 4 / 256, 256>>>();
    k_reduce<<<dim3(32, NB), 256>>>(x);
    k_mid<<<384, 128>>>(w10, w11, gamma, beta, mean, var, w20, w21);
    k_final<<<dim3(NC, NB), 256>>>(x, out);
}